// round 11
// baseline (speedup 1.0000x reference)
#include <cuda_runtime.h>

// SplineLoss on GB300: reference samples the spline only at integer knot
// times (t = 0,10,...,1020) where dx == 0.0 exactly, so all moment terms
// vanish: loss == mean over s,b,d of (true[b,10s,d]-pred[b,10s,d])^2.
//
// R11: minimal CTA tail. Every prior round paid smem+BAR+warp0-epilogue
// (~200cy) per block. Here each WARP independently does: integer REDUX of
// its quantized partial -> one fused u64 atomic into 1 of 32 spread bins.
// No __syncthreads, no shared memory, CTA exits immediately.
//  - 824 blocks x 256 thr, one float4-pair per thread (single wave)
//  - per-thread fixed-point at 2^21: integer adds are exact & commutative
//    -> bit-deterministic result (measured rel_err 0.0 with this scheme)
//  - 32 bins on distinct 256B lines: 206 atomics/address, parallel slices
//  - bin-last warp (count==206) forwards exact bin total; final fold
//    (count==32) writes the mean.

#define T_ 1024
#define D4_ 16                   // 64 floats per row = 16 float4
#define S_ 103                   // sample times 0,10,...,1020
#define ROW_STRIDE4_ (T_ * D4_)  // float4 stride between batches
#define COUNT_ 843776.0          // 128 * 103 * 64
#define FIX_SCALE 2097152.0      // 2^21

constexpr int NBLK  = 8 * S_;    // 824 blocks, 8 per sample time
constexpr int NTHR  = 256;       // 16 batches x 16 float4
constexpr int NBINS = 32;
constexpr int NWARPS_TOTAL = NBLK * (NTHR / 32);      // 6592
constexpr int BINSZ = NWARPS_TOTAL / NBINS;           // 206

__device__ __align__(256) unsigned long long g_bins[NBINS * 32]; // [i*32]
__device__ __align__(256) unsigned long long g_final = 0;

__device__ __forceinline__ unsigned warp_redux_add_u32(unsigned x) {
    unsigned r;
    asm volatile("redux.sync.add.u32 %0, %1, 0xffffffff;"
                 : "=r"(r) : "r"(x));
    return r;
}

__global__ __launch_bounds__(NTHR) void spline_mse_r11(
    const float* __restrict__ yt, const float* __restrict__ yp,
    float* __restrict__ out)
{
    const int s = blockIdx.x >> 3;             // 0..102
    const int q = blockIdx.x & 7;              // batch group [16q, 16q+16)
    const int d4   = threadIdx.x & (D4_ - 1);
    const int brel = threadIdx.x >> 4;         // 0..15

    const int addr = s * 10 * D4_ + (q * 16 + brel) * ROW_STRIDE4_ + d4;
    const float4 va = __ldg((const float4*)yt + addr);
    const float4 vb = __ldg((const float4*)yp + addr);

    float e0 = va.x - vb.x;
    float e1 = va.y - vb.y;
    float e2 = va.z - vb.z;
    float e3 = va.w - vb.w;
    float acc = e0 * e0;
    acc = fmaf(e1, e1, acc);
    acc = fmaf(e2, e2, acc);
    acc = fmaf(e3, e3, acc);

    // per-thread fixed-point quantization (deterministic)
    unsigned fx = __float2uint_rn(acc * (float)FIX_SCALE);

    // warp reduce: one instruction, exact
    fx = warp_redux_add_u32(fx);

    if ((threadIdx.x & 31) != 0) return;       // lane 0 of each warp only

    // level 1: per-warp atomic into spread bin (206 ops per address)
    const int gwid = blockIdx.x * (NTHR / 32) + (threadIdx.x >> 5);
    unsigned long long fixed = (unsigned long long)fx;   // exact warp sum
    unsigned long long* bin = &g_bins[(gwid & (NBINS - 1)) * 32];
    unsigned long long old = atomicAdd(bin, (fixed << 16) | 1ull);

    if ((old & 0xFFFFull) != (unsigned long long)(BINSZ - 1)) return;

    // bin-last warp: forward exact bin total, reset bin for next replay
    unsigned long long bin_total = (old >> 16) + fixed;
    *bin = 0ull;                                         // no later readers
    unsigned long long fold = atomicAdd(&g_final, (bin_total << 16) | 1ull);

    if ((fold & 0xFFFFull) == (unsigned long long)(NBINS - 1)) {
        unsigned long long total = (fold >> 16) + bin_total;
        out[0] = (float)((double)total / (FIX_SCALE * COUNT_));
        g_final = 0ull;                                  // reset for replay
    }
}

extern "C" void kernel_launch(void* const* d_in, const int* in_sizes, int n_in,
                              void* d_out, int out_size)
{
    const float* yt = (const float*)d_in[0];   // true_frames
    const float* yp = (const float*)d_in[1];   // predicted_frames
    spline_mse_r11<<<NBLK, NTHR>>>(yt, yp, (float*)d_out);
}

// round 12
// speedup vs baseline: 1.0435x; 1.0435x over previous
#include <cuda_runtime.h>

// SplineLoss on GB300: reference samples the spline only at integer knot
// times (t = 0,10,...,1020) where dx == 0.0 exactly, so all moment terms
// vanish: loss == mean over s,b,d of (true[b,10s,d]-pred[b,10s,d])^2.
//
// R12 = R7 champion (824x256 single wave, SHFL trees, 8-bin two-level
// deterministic fixed-point atomic tail) + epilogue reorder: the bin-last
// block issues the fold ATOMG (318cy RT, critical) BEFORE the bin-reset
// STG so the store lands in the atomic's shadow.
// Measured facts honored: SHFL tree beats REDUX (-0.25us), block tail
// beats warp-level atomics, two-level beats single-level.

#define T_ 1024
#define D4_ 16                   // 64 floats per row = 16 float4
#define S_ 103                   // sample times 0,10,...,1020
#define ROW_STRIDE4_ (T_ * D4_)  // float4 stride between batches
#define COUNT_ 843776.0          // 128 * 103 * 64
#define FIX_SCALE 16777216.0     // 2^24

constexpr int NBLK  = 8 * S_;    // 824 blocks, 8 per sample time
constexpr int NTHR  = 256;       // 16 batches x 16 float4
constexpr int NBINS = 8;
constexpr int BINSZ = NBLK / NBINS;   // 103

__device__ __align__(256) unsigned long long g_bins[NBINS * 32]; // use [i*32]
__device__ __align__(256) unsigned long long g_final = 0;

__global__ __launch_bounds__(NTHR) void spline_mse_r12(
    const float* __restrict__ yt, const float* __restrict__ yp,
    float* __restrict__ out)
{
    const int s = blockIdx.x >> 3;             // 0..102
    const int q = blockIdx.x & 7;              // batch group [16q, 16q+16)
    const int d4   = threadIdx.x & (D4_ - 1);
    const int brel = threadIdx.x >> 4;         // 0..15

    const int addr = s * 10 * D4_ + (q * 16 + brel) * ROW_STRIDE4_ + d4;
    const float4 va = __ldg((const float4*)yt + addr);
    const float4 vb = __ldg((const float4*)yp + addr);

    float e0 = va.x - vb.x;
    float e1 = va.y - vb.y;
    float e2 = va.z - vb.z;
    float e3 = va.w - vb.w;
    float acc = e0 * e0;
    acc = fmaf(e1, e1, acc);
    acc = fmaf(e2, e2, acc);
    acc = fmaf(e3, e3, acc);

    // block reduce (fixed order -> deterministic)
    #pragma unroll
    for (int o = 16; o > 0; o >>= 1)
        acc += __shfl_down_sync(0xffffffffu, acc, o);

    __shared__ float sh[NTHR / 32];
    if ((threadIdx.x & 31) == 0) sh[threadIdx.x >> 5] = acc;
    __syncthreads();

    if (threadIdx.x != 0) return;              // thread 0 only past here

    float v = sh[0];
    #pragma unroll
    for (int w = 1; w < NTHR / 32; w++) v += sh[w];

    // level 1: bin atomic (103 blocks per address, 8 addresses in parallel)
    unsigned long long fixed =
        __double2ull_rn((double)v * FIX_SCALE);          // v >= 0, exact int
    unsigned long long* bin = &g_bins[(blockIdx.x & (NBINS - 1)) * 32];
    unsigned long long old = atomicAdd(bin, (fixed << 16) | 1ull);

    if ((old & 0xFFFFull) != (unsigned long long)(BINSZ - 1)) return;

    // bin-last: fold FIRST (critical ATOMG), then reset bin in its shadow
    unsigned long long bin_total = (old >> 16) + fixed;
    unsigned long long fold = atomicAdd(&g_final, (bin_total << 16) | 1ull);
    *bin = 0ull;                                         // next-replay reset

    if ((fold & 0xFFFFull) == (unsigned long long)(NBINS - 1)) {
        unsigned long long total = (fold >> 16) + bin_total;
        out[0] = (float)((double)total / (FIX_SCALE * COUNT_));
        g_final = 0ull;                                  // reset for replay
    }
}

extern "C" void kernel_launch(void* const* d_in, const int* in_sizes, int n_in,
                              void* d_out, int out_size)
{
    const float* yt = (const float*)d_in[0];   // true_frames
    const float* yp = (const float*)d_in[1];   // predicted_frames
    spline_mse_r12<<<NBLK, NTHR>>>(yt, yp, (float*)d_out);
}